// round 1
// baseline (speedup 1.0000x reference)
#include <cuda_runtime.h>

#define NMAX 50000
#define F 512
#define H 128

// ---- scratch (static device globals: no allocation allowed) ----
__device__ float g_x[(size_t)NMAX * H];      // (h*out_norm) @ W
__device__ float g_agg[(size_t)NMAX * H];    // scatter accumulator
__device__ int   g_deg_out[NMAX];
__device__ int   g_deg_in[NMAX];
__device__ float g_out_norm[NMAX];
__device__ float g_in_norm[NMAX];

// ---- zero accumulators (must happen every launch: graph replays) ----
__global__ void zero_kernel(int n) {
    int total4 = n * (H / 4);
    float4 z = make_float4(0.f, 0.f, 0.f, 0.f);
    for (int i = blockIdx.x * blockDim.x + threadIdx.x; i < total4;
         i += gridDim.x * blockDim.x) {
        reinterpret_cast<float4*>(g_agg)[i] = z;
        if (i < n) { g_deg_out[i] = 0; g_deg_in[i] = 0; }
    }
}

// ---- degree histograms ----
__global__ void deg_kernel(const int* __restrict__ src,
                           const int* __restrict__ dst, int e) {
    int i = blockIdx.x * blockDim.x + threadIdx.x;
    if (i < e) {
        atomicAdd(&g_deg_out[src[i]], 1);
        atomicAdd(&g_deg_in[dst[i]], 1);
    }
}

// ---- deg -> norm ----
__global__ void norm_kernel(int n) {
    int i = blockIdx.x * blockDim.x + threadIdx.x;
    if (i < n) {
        g_out_norm[i] = rsqrtf((float)max(g_deg_out[i], 1));
        g_in_norm[i]  = rsqrtf((float)max(g_deg_in[i], 1));
    }
}

// ---- GEMM: g_x = (h * out_norm[:,None]) @ W ; [n,512]@[512,128] ----
// Block tile 64x128, K-tile 32, 256 threads, per-thread 8x4 outputs.
__global__ __launch_bounds__(256) void gemm_kernel(const float* __restrict__ hin,
                                                   const float* __restrict__ W,
                                                   int n) {
    __shared__ float As[64][32];
    __shared__ float Bs[32][128];

    const int tid  = threadIdx.x;
    const int tx   = tid & 31;   // output col group: cols tx*4..tx*4+3
    const int ty   = tid >> 5;   // output row group: rows ty*8..ty*8+7
    const int brow = blockIdx.x * 64;

    float acc[8][4];
#pragma unroll
    for (int r = 0; r < 8; r++)
#pragma unroll
        for (int c = 0; c < 4; c++) acc[r][c] = 0.f;

    // A-load mapping: thread -> (row, 4 k's); two passes cover 64 rows
    const int a_row = tid >> 3;        // 0..31
    const int a_k4  = (tid & 7) * 4;   // 0,4,..,28
    // B-load mapping: thread -> (k row, 4 cols); four passes cover 32 k's
    const int b_k  = tid >> 5;         // 0..7
    const int b_c4 = (tid & 31) * 4;   // 0..124

    const int  r0ok = (brow + a_row) < n;
    const int  r1ok = (brow + a_row + 32) < n;
    const float s0 = r0ok ? g_out_norm[brow + a_row] : 0.f;
    const float s1 = r1ok ? g_out_norm[brow + a_row + 32] : 0.f;

    for (int k0 = 0; k0 < F; k0 += 32) {
        float4 a0 = make_float4(0.f, 0.f, 0.f, 0.f);
        float4 a1 = make_float4(0.f, 0.f, 0.f, 0.f);
        if (r0ok)
            a0 = *reinterpret_cast<const float4*>(
                &hin[(size_t)(brow + a_row) * F + k0 + a_k4]);
        if (r1ok)
            a1 = *reinterpret_cast<const float4*>(
                &hin[(size_t)(brow + a_row + 32) * F + k0 + a_k4]);
        a0.x *= s0; a0.y *= s0; a0.z *= s0; a0.w *= s0;
        a1.x *= s1; a1.y *= s1; a1.z *= s1; a1.w *= s1;
        *reinterpret_cast<float4*>(&As[a_row][a_k4])      = a0;
        *reinterpret_cast<float4*>(&As[a_row + 32][a_k4]) = a1;

#pragma unroll
        for (int i = 0; i < 4; i++) {
            int kk = b_k + i * 8;
            *reinterpret_cast<float4*>(&Bs[kk][b_c4]) =
                *reinterpret_cast<const float4*>(&W[(size_t)(k0 + kk) * H + b_c4]);
        }
        __syncthreads();

#pragma unroll
        for (int k4 = 0; k4 < 32; k4 += 4) {
            float4 av[8];
#pragma unroll
            for (int r = 0; r < 8; r++)
                av[r] = *reinterpret_cast<float4*>(&As[ty * 8 + r][k4]);
#pragma unroll
            for (int j = 0; j < 4; j++) {
                float4 bv = *reinterpret_cast<float4*>(&Bs[k4 + j][tx * 4]);
#pragma unroll
                for (int r = 0; r < 8; r++) {
                    float a = (j == 0) ? av[r].x : (j == 1) ? av[r].y
                              : (j == 2) ? av[r].z : av[r].w;
                    acc[r][0] += a * bv.x;
                    acc[r][1] += a * bv.y;
                    acc[r][2] += a * bv.z;
                    acc[r][3] += a * bv.w;
                }
            }
        }
        __syncthreads();
    }

#pragma unroll
    for (int r = 0; r < 8; r++) {
        int gr = brow + ty * 8 + r;
        if (gr < n) {
            float4 o = make_float4(acc[r][0], acc[r][1], acc[r][2], acc[r][3]);
            *reinterpret_cast<float4*>(&g_x[(size_t)gr * H + tx * 4]) = o;
        }
    }
}

// ---- edge scatter: agg[dst] += x[src] ; one warp per edge, v4 reductions ----
__global__ __launch_bounds__(256) void scatter_kernel(const int* __restrict__ src,
                                                      const int* __restrict__ dst,
                                                      int e) {
    int edge = blockIdx.x * 8 + (threadIdx.x >> 5);
    if (edge >= e) return;
    int lane = threadIdx.x & 31;
    int s = src[edge];
    int d = dst[edge];
    float4 v = *reinterpret_cast<const float4*>(&g_x[(size_t)s * H + lane * 4]);
    float* p = &g_agg[(size_t)d * H + lane * 4];
    asm volatile("red.global.add.v4.f32 [%0], {%1, %2, %3, %4};"
                 :: "l"(p), "f"(v.x), "f"(v.y), "f"(v.z), "f"(v.w)
                 : "memory");
}

// ---- fused in_norm + bias + LayerNorm: warp per node ----
__global__ __launch_bounds__(256) void ln_kernel(const float* __restrict__ bias,
                                                 const float* __restrict__ gamma,
                                                 const float* __restrict__ beta,
                                                 float* __restrict__ y, int n) {
    int node = blockIdx.x * 8 + (threadIdx.x >> 5);
    if (node >= n) return;
    int lane = threadIdx.x & 31;

    float s = g_in_norm[node];
    float4 v  = *reinterpret_cast<const float4*>(&g_agg[(size_t)node * H + lane * 4]);
    float4 bb = *reinterpret_cast<const float4*>(&bias[lane * 4]);
    v.x = v.x * s + bb.x;
    v.y = v.y * s + bb.y;
    v.z = v.z * s + bb.z;
    v.w = v.w * s + bb.w;

    float sum = v.x + v.y + v.z + v.w;
#pragma unroll
    for (int o = 16; o; o >>= 1) sum += __shfl_xor_sync(0xffffffffu, sum, o);
    float mu = sum * (1.f / 128.f);

    float dx = v.x - mu, dy = v.y - mu, dz = v.z - mu, dw = v.w - mu;
    float sq = dx * dx + dy * dy + dz * dz + dw * dw;
#pragma unroll
    for (int o = 16; o; o >>= 1) sq += __shfl_xor_sync(0xffffffffu, sq, o);
    float rstd = rsqrtf(sq * (1.f / 128.f) + 1e-5f);

    float4 g  = *reinterpret_cast<const float4*>(&gamma[lane * 4]);
    float4 be = *reinterpret_cast<const float4*>(&beta[lane * 4]);
    float4 o4;
    o4.x = dx * rstd * g.x + be.x;
    o4.y = dy * rstd * g.y + be.y;
    o4.z = dz * rstd * g.z + be.z;
    o4.w = dw * rstd * g.w + be.w;
    *reinterpret_cast<float4*>(&y[(size_t)node * H + lane * 4]) = o4;
}

extern "C" void kernel_launch(void* const* d_in, const int* in_sizes, int n_in,
                              void* d_out, int out_size) {
    const float* h     = (const float*)d_in[0];
    const int*   src   = (const int*)d_in[1];
    const int*   dst   = (const int*)d_in[2];
    const float* W     = (const float*)d_in[3];
    const float* b     = (const float*)d_in[4];
    const float* gamma = (const float*)d_in[5];
    const float* beta  = (const float*)d_in[6];
    float* y = (float*)d_out;

    int n = in_sizes[0] / F;   // 50000
    int e = in_sizes[1];       // 800000

    zero_kernel<<<1024, 256>>>(n);
    deg_kernel<<<(e + 255) / 256, 256>>>(src, dst, e);
    norm_kernel<<<(n + 255) / 256, 256>>>(n);
    gemm_kernel<<<(n + 63) / 64, 256>>>(h, W, n);
    scatter_kernel<<<(e + 7) / 8, 256>>>(src, dst, e);
    ln_kernel<<<(n + 7) / 8, 256>>>(b, gamma, beta, y, n);
}